// round 8
// baseline (speedup 1.0000x reference)
#include <cuda_runtime.h>
#include <cuda_bf16.h>
#include <cstdint>
#include <math.h>

#define Tn 4096
#define Dn 1024
#define Hn 4096
#define En 8
#define NSn 2
#define NEn (En + NSn)
#define ROUTED_ROWS (2 * Tn)
#define ALLROWS (ROUTED_ROWS + NSn * Tn)

// ---- static scratch (no allocation APIs); aligned for cp.async 16B ----
__device__ __align__(1024) __nv_bfloat16 g_Xe[(size_t)Tn * 2 * Dn];      // x hi|lo [t][2D]
// Shared weight buffer: W1^T hi|lo [z][H][2D] during FFN1, then W2^T hi|lo [z][D][2H].
__device__ __align__(1024) __nv_bfloat16 g_We[(size_t)NEn * Hn * 2 * Dn];
__device__ __align__(1024) __nv_bfloat16 g_He[(size_t)ALLROWS * 2 * Hn]; // hidden hi|lo
__device__ int g_cnt[En];
__device__ int g_off[En];
__device__ int g_list[En * Tn];

// ---------------- PTX helpers (non-'a' features only) ----------------
__device__ __forceinline__ uint32_t smem_u32(const void* p) {
    uint32_t a;
    asm("{ .reg .u64 t; cvta.to.shared.u64 t, %1; cvt.u32.u64 %0, t; }" : "=r"(a) : "l"(p));
    return a;
}
__device__ __forceinline__ void cp16(uint32_t s, const void* g) {
    asm volatile("cp.async.cg.shared.global [%0], [%1], 16;" :: "r"(s), "l"(g));
}
__device__ __forceinline__ void ldsm4(uint32_t* r, uint32_t a) {
    asm volatile("ldmatrix.sync.aligned.m8n8.x4.shared.b16 {%0,%1,%2,%3}, [%4];"
                 : "=r"(r[0]), "=r"(r[1]), "=r"(r[2]), "=r"(r[3]) : "r"(a));
}
__device__ __forceinline__ void mma16816(float* d, const uint32_t* a, uint32_t b0, uint32_t b1) {
    asm volatile(
        "mma.sync.aligned.m16n8k16.row.col.f32.bf16.bf16.f32 "
        "{%0,%1,%2,%3}, {%4,%5,%6,%7}, {%8,%9}, {%0,%1,%2,%3};"
        : "+f"(d[0]), "+f"(d[1]), "+f"(d[2]), "+f"(d[3])
        : "r"(a[0]), "r"(a[1]), "r"(a[2]), "r"(a[3]), "r"(b0), "r"(b1));
}
__device__ __forceinline__ float gelu_f(float v) {
    float u = 0.7978845608028654f * (v + 0.044715f * v * v * v);
    float t;
    asm("tanh.approx.f32 %0, %1;" : "=f"(t) : "f"(u));
    return 0.5f * v * (1.0f + t);
}

// ---------------- router ----------------
__global__ void zero_cnt_kernel() {
    if (threadIdx.x < En) g_cnt[threadIdx.x] = 0;
}
__global__ void prefix_kernel() {
    if (threadIdx.x == 0) {
        int s = 0;
#pragma unroll
        for (int e = 0; e < En; e++) { g_off[e] = s; s += g_cnt[e]; }
    }
}
__global__ void router_kernel(const float* __restrict__ x,
                              const float* __restrict__ Wr,
                              const float* __restrict__ br,
                              const float* __restrict__ gum) {
    int t = blockIdx.x;
    int tid = threadIdx.x;  // 128
    const float* xr = x + (size_t)t * Dn;
    float acc[En];
#pragma unroll
    for (int e = 0; e < En; e++) acc[e] = 0.f;
    for (int d = tid; d < Dn; d += 128) {
        float xv = xr[d];
        float4 w0 = *(const float4*)(Wr + d * En);
        float4 w1 = *(const float4*)(Wr + d * En + 4);
        acc[0] += xv * w0.x; acc[1] += xv * w0.y;
        acc[2] += xv * w0.z; acc[3] += xv * w0.w;
        acc[4] += xv * w1.x; acc[5] += xv * w1.y;
        acc[6] += xv * w1.z; acc[7] += xv * w1.w;
    }
#pragma unroll
    for (int e = 0; e < En; e++) {
#pragma unroll
        for (int off = 16; off; off >>= 1)
            acc[e] += __shfl_down_sync(0xffffffffu, acc[e], off);
    }
    __shared__ float red[4][En];
    if ((tid & 31) == 0) {
#pragma unroll
        for (int e = 0; e < En; e++) red[tid >> 5][e] = acc[e];
    }
    __syncthreads();
    if (tid == 0) {
        float s[En];
#pragma unroll
        for (int e = 0; e < En; e++)
            s[e] = red[0][e] + red[1][e] + red[2][e] + red[3][e]
                 + br[e] + gum[(size_t)t * En + e];
        int i1 = 0;
#pragma unroll
        for (int e = 1; e < En; e++) if (s[e] > s[i1]) i1 = e;
        int i2 = (i1 == 0) ? 1 : 0;
#pragma unroll
        for (int e = 0; e < En; e++)
            if (e != i1 && s[e] > s[i2]) i2 = e;
        int p1 = atomicAdd(&g_cnt[i1], 1); g_list[i1 * Tn + p1] = t;
        int p2 = atomicAdd(&g_cnt[i2], 1); g_list[i2 * Tn + p2] = t;
    }
}

// ---------------- hi/lo conversions ----------------
__global__ void ext_x_kernel(const float* __restrict__ x) {
    int idx = blockIdx.x * 256 + threadIdx.x;
    if (idx >= Tn * Dn) return;
    int t = idx / Dn, d = idx - t * Dn;
    float v = x[idx];
    __nv_bfloat16 hi = __float2bfloat16(v);
    g_Xe[(size_t)t * (2 * Dn) + d] = hi;
    g_Xe[(size_t)t * (2 * Dn) + Dn + d] = __float2bfloat16(v - __bfloat162float(hi));
}

// Transpose + split: src [z][SK][SN] fp32 -> g_We [zBase+z][SN][2*SK] bf16 (hi @ +0, lo @ +SK)
template <int SK, int SN>
__global__ void ext_w_kernel(const float* __restrict__ W, int zBase) {
    __shared__ float tile[32][33];
    int n0 = blockIdx.x * 32, k0 = blockIdx.y * 32;
    const float* Wz = W + (size_t)blockIdx.z * SK * SN;
    __nv_bfloat16* dst = g_We + (size_t)(zBase + blockIdx.z) * SN * (size_t)(2 * SK);
    int tx = threadIdx.x, ty = threadIdx.y;
#pragma unroll
    for (int r = 0; r < 32; r += 8)
        tile[ty + r][tx] = Wz[(size_t)(k0 + ty + r) * SN + n0 + tx];
    __syncthreads();
#pragma unroll
    for (int r = 0; r < 32; r += 8) {
        float v = tile[tx][ty + r];
        __nv_bfloat16 hi = __float2bfloat16(v);
        size_t o = (size_t)(n0 + ty + r) * (2 * SK) + (k0 + tx);
        dst[o] = hi;
        dst[o + SK] = __float2bfloat16(v - __bfloat162float(hi));
    }
}

// ---------------- mma.sync GEMM: BM=128, BN=256, warp tile 64x64 ----------------
#define BM 128
#define BN 256
#define BK 32
#define STAGES 3
#define ROWPB 80                      // padded row pitch in bytes (40 bf16)
#define TILEA (128 * ROWPB)           // 10240 B
#define TILEB (256 * ROWPB)           // 20480 B
#define STGB (TILEA + TILEB)          // 30720 B per stage
#define SMEMT (STAGES * STGB)         // 92160 B

// IS1: He[row] = split(gelu(X@W1+b1));  !IS1: out[tok] += H@W2+b2
template <int KD, int NT, bool GATHER, bool IS1>
__global__ void __launch_bounds__(256, 1)
moe_gemm(const float* __restrict__ bias, float* __restrict__ outF) {
    int z = blockIdx.z;
    int M = GATHER ? g_cnt[z] : Tn;
    int m0 = blockIdx.y * BM;
    if (m0 >= M) return;
    int n0 = blockIdx.x * BN;
    int tid = threadIdx.x, lane = tid & 31, wid = tid >> 5;
    int wm = wid & 1, wn = wid >> 1;     // 2 x 4 warp grid; warp tile 64m x 64n

    extern __shared__ __align__(1024) char smem[];
    uint32_t sb = smem_u32(smem);

    size_t rowBase = GATHER ? (size_t)g_off[z] : (size_t)(ROUTED_ROWS + (size_t)z * Tn);
    // A loader: row = tid>>1, 32B half = (tid&1)
    int arow = m0 + (tid >> 1);
    int rr = (arow < M) ? arow : (M - 1);
    const __nv_bfloat16* aRow;
    if (IS1) {
        int tok = GATHER ? g_list[z * Tn + rr] : rr;
        aRow = g_Xe + (size_t)tok * (2 * KD);
    } else {
        aRow = g_He + (rowBase + rr) * (size_t)(2 * KD);
    }
    int zw = GATHER ? z : (En + z);
    // B loader: rows tid>>1 and 128+(tid>>1)
    const __nv_bfloat16* bRow0 = g_We + ((size_t)zw * NT + n0 + (tid >> 1)) * (size_t)(2 * KD);
    const __nv_bfloat16* bRow1 = bRow0 + (size_t)128 * (2 * KD);

    const int IT = KD / BK;
    const int nIter = 3 * IT;   // segments: Ah*Bh, Al*Bh, Ah*Bl
    uint32_t stA = sb + (tid >> 1) * ROWPB + (tid & 1) * 32;
    uint32_t stB0 = sb + TILEA + (tid >> 1) * ROWPB + (tid & 1) * 32;
    uint32_t stB1 = stB0 + 128 * ROWPB;
    int ldCol = (tid & 1) * 16;

    float d[4][8][4];
#pragma unroll
    for (int a = 0; a < 4; a++)
#pragma unroll
        for (int b = 0; b < 8; b++)
#pragma unroll
            for (int c = 0; c < 4; c++) d[a][b][c] = 0.f;

    auto loadStage = [&](int j, int s) {
        int seg = j / IT, kk = j - seg * IT;
        int aOff = ((seg == 1) ? KD : 0) + kk * BK + ldCol;
        int bOff = ((seg == 2) ? KD : 0) + kk * BK + ldCol;
        uint32_t off = s * STGB;
        cp16(stA + off,       aRow + aOff);
        cp16(stA + off + 16,  aRow + aOff + 8);
        cp16(stB0 + off,      bRow0 + bOff);
        cp16(stB0 + off + 16, bRow0 + bOff + 8);
        cp16(stB1 + off,      bRow1 + bOff);
        cp16(stB1 + off + 16, bRow1 + bOff + 8);
    };

    loadStage(0, 0);
    asm volatile("cp.async.commit_group;" ::: "memory");
    loadStage(1, 1);
    asm volatile("cp.async.commit_group;" ::: "memory");

    int lrow = lane & 15, lcol = (lane >> 4) * 16;
    for (int j = 0; j < nIter; j++) {
        int s = j % STAGES;
        asm volatile("cp.async.wait_group 1;" ::: "memory");
        __syncthreads();
        int jn = j + 2;
        if (jn < nIter) loadStage(jn, jn % STAGES);
        asm volatile("cp.async.commit_group;" ::: "memory");

        uint32_t Ab = sb + s * STGB;
        uint32_t Bb = Ab + TILEA;
#pragma unroll
        for (int k16 = 0; k16 < 2; k16++) {
            uint32_t af[4][4];
#pragma unroll
            for (int mi = 0; mi < 4; mi++)
                ldsm4(af[mi], Ab + (wm * 64 + mi * 16 + lrow) * ROWPB + k16 * 32 + lcol);
            uint32_t bf[4][4];
#pragma unroll
            for (int g = 0; g < 4; g++)
                ldsm4(bf[g], Bb + (wn * 64 + g * 16 + lrow) * ROWPB + k16 * 32 + lcol);
#pragma unroll
            for (int mi = 0; mi < 4; mi++)
#pragma unroll
                for (int t = 0; t < 8; t++) {
                    int g = t >> 1, w = t & 1;
                    mma16816(d[mi][t], af[mi], bf[g][w], bf[g][2 + w]);
                }
        }
    }

    // ---- epilogue ----
    const float* bz = bias + (size_t)z * NT;
    int cb = n0 + wn * 64 + (lane & 3) * 2;
    int r0 = m0 + wm * 64 + (lane >> 2);
#pragma unroll
    for (int mi = 0; mi < 4; mi++) {
#pragma unroll
        for (int half = 0; half < 2; half++) {   // regs {0,1} row r, {2,3} row r+8
            int row = r0 + mi * 16 + half * 8;
            if (row >= M) continue;
            if (IS1) {
                __nv_bfloat16* dstH = g_He + (rowBase + row) * (size_t)(2 * NT);
#pragma unroll
                for (int ni = 0; ni < 8; ni++) {
                    int col = cb + ni * 8;
                    float v0 = gelu_f(d[mi][ni][half * 2 + 0] + bz[col]);
                    float v1 = gelu_f(d[mi][ni][half * 2 + 1] + bz[col + 1]);
                    __nv_bfloat16 h0 = __float2bfloat16(v0);
                    __nv_bfloat16 h1 = __float2bfloat16(v1);
                    __nv_bfloat16 l0 = __float2bfloat16(v0 - __bfloat162float(h0));
                    __nv_bfloat16 l1 = __float2bfloat16(v1 - __bfloat162float(h1));
                    uint32_t ph = ((uint32_t)*(uint16_t*)&h1 << 16) | *(uint16_t*)&h0;
                    uint32_t pl = ((uint32_t)*(uint16_t*)&l1 << 16) | *(uint16_t*)&l0;
                    *(uint32_t*)(dstH + col) = ph;
                    *(uint32_t*)(dstH + NT + col) = pl;
                }
            } else {
                int g = GATHER ? g_list[z * Tn + row] : row;
                float* od = outF + (size_t)g * Dn;
#pragma unroll
                for (int ni = 0; ni < 8; ni++) {
                    int col = cb + ni * 8;
                    atomicAdd(&od[col],     d[mi][ni][half * 2 + 0] + bz[col]);
                    atomicAdd(&od[col + 1], d[mi][ni][half * 2 + 1] + bz[col + 1]);
                }
            }
        }
    }
}

extern "C" void kernel_launch(void* const* d_in, const int* in_sizes, int n_in,
                              void* d_out, int out_size) {
    const float* x   = (const float*)d_in[0];
    const float* Ws1 = (const float*)d_in[1];
    const float* bs1 = (const float*)d_in[2];
    const float* Ws2 = (const float*)d_in[3];
    const float* bs2 = (const float*)d_in[4];
    const float* We1 = (const float*)d_in[5];
    const float* be1 = (const float*)d_in[6];
    const float* We2 = (const float*)d_in[7];
    const float* be2 = (const float*)d_in[8];
    const float* Wr  = (const float*)d_in[9];
    const float* br  = (const float*)d_in[10];
    const float* gum = (const float*)d_in[11];
    float* out = (float*)d_out;

    cudaFuncSetAttribute(moe_gemm<Dn, Hn, true,  true >, cudaFuncAttributeMaxDynamicSharedMemorySize, SMEMT);
    cudaFuncSetAttribute(moe_gemm<Dn, Hn, false, true >, cudaFuncAttributeMaxDynamicSharedMemorySize, SMEMT);
    cudaFuncSetAttribute(moe_gemm<Hn, Dn, true,  false>, cudaFuncAttributeMaxDynamicSharedMemorySize, SMEMT);
    cudaFuncSetAttribute(moe_gemm<Hn, Dn, false, false>, cudaFuncAttributeMaxDynamicSharedMemorySize, SMEMT);

    cudaMemsetAsync(out, 0, (size_t)out_size * sizeof(float), 0);
    zero_cnt_kernel<<<1, 32>>>();
    router_kernel<<<Tn, 128>>>(x, Wr, br, gum);
    prefix_kernel<<<1, 32>>>();

    ext_x_kernel<<<(Tn * Dn) / 256, 256>>>(x);
    dim3 bw(32, 8);

    // Phase 1: W1^T into g_We, then FFN1 (routed + shared).
    ext_w_kernel<Dn, Hn><<<dim3(Hn / 32, Dn / 32, En ), bw>>>(We1, 0);
    ext_w_kernel<Dn, Hn><<<dim3(Hn / 32, Dn / 32, NSn), bw>>>(Ws1, En);
    moe_gemm<Dn, Hn, true,  true ><<<dim3(Hn / BN, Tn / BM, En ), 256, SMEMT>>>(be1, nullptr);
    moe_gemm<Dn, Hn, false, true ><<<dim3(Hn / BN, Tn / BM, NSn), 256, SMEMT>>>(bs1, nullptr);

    // Phase 2: W2^T overwrites g_We (stream-ordered after FFN1), then FFN2.
    ext_w_kernel<Hn, Dn><<<dim3(Dn / 32, Hn / 32, En ), bw>>>(We2, 0);
    ext_w_kernel<Hn, Dn><<<dim3(Dn / 32, Hn / 32, NSn), bw>>>(Ws2, En);
    moe_gemm<Hn, Dn, true,  false><<<dim3(Dn / BN, Tn / BM, En ), 256, SMEMT>>>(be2, out);
    moe_gemm<Hn, Dn, false, false><<<dim3(Dn / BN, Tn / BM, NSn), 256, SMEMT>>>(bs2, out);
}

// round 9
// speedup vs baseline: 1.6098x; 1.6098x over previous
#include <cuda_runtime.h>
#include <cuda_fp16.h>
#include <cstdint>
#include <math.h>

#define Tn 4096
#define Dn 1024
#define Hn 4096
#define En 8
#define NSn 2
#define NEn (En + NSn)
#define ROUTED_ROWS (2 * Tn)
#define ALLROWS (ROUTED_ROWS + NSn * Tn)

// ---- static scratch (no allocation APIs); aligned for cp.async 16B ----
__device__ __align__(1024) __half g_Xe[(size_t)Tn * 2 * Dn];      // x hi|lo fp16 [t][2D]
// Shared weight buffer: W1^T fp16 [z][H][D] during FFN1, then W2^T fp16 [z][D][H]. (80MB)
__device__ __align__(1024) __half g_We[(size_t)NEn * Hn * Dn];
__device__ __align__(1024) __half g_He[(size_t)ALLROWS * 2 * Hn];  // hidden hi|lo fp16
__device__ int g_cnt[En];
__device__ int g_off[En];
__device__ int g_list[En * Tn];

// ---------------- PTX helpers (non-'a' features only) ----------------
__device__ __forceinline__ uint32_t smem_u32(const void* p) {
    uint32_t a;
    asm("{ .reg .u64 t; cvta.to.shared.u64 t, %1; cvt.u32.u64 %0, t; }" : "=r"(a) : "l"(p));
    return a;
}
__device__ __forceinline__ void cp16(uint32_t s, const void* g) {
    asm volatile("cp.async.cg.shared.global [%0], [%1], 16;" :: "r"(s), "l"(g));
}
__device__ __forceinline__ void ldsm4(uint32_t* r, uint32_t a) {
    asm volatile("ldmatrix.sync.aligned.m8n8.x4.shared.b16 {%0,%1,%2,%3}, [%4];"
                 : "=r"(r[0]), "=r"(r[1]), "=r"(r[2]), "=r"(r[3]) : "r"(a));
}
__device__ __forceinline__ void mma16816(float* d, const uint32_t* a, uint32_t b0, uint32_t b1) {
    asm volatile(
        "mma.sync.aligned.m16n8k16.row.col.f32.f16.f16.f32 "
        "{%0,%1,%2,%3}, {%4,%5,%6,%7}, {%8,%9}, {%0,%1,%2,%3};"
        : "+f"(d[0]), "+f"(d[1]), "+f"(d[2]), "+f"(d[3])
        : "r"(a[0]), "r"(a[1]), "r"(a[2]), "r"(a[3]), "r"(b0), "r"(b1));
}
__device__ __forceinline__ float gelu_f(float v) {
    float u = 0.7978845608028654f * (v + 0.044715f * v * v * v);
    float t;
    asm("tanh.approx.f32 %0, %1;" : "=f"(t) : "f"(u));
    return 0.5f * v * (1.0f + t);
}

// ---------------- router ----------------
__global__ void zero_cnt_kernel() {
    if (threadIdx.x < En) g_cnt[threadIdx.x] = 0;
}
__global__ void prefix_kernel() {
    if (threadIdx.x == 0) {
        int s = 0;
#pragma unroll
        for (int e = 0; e < En; e++) { g_off[e] = s; s += g_cnt[e]; }
    }
}
__global__ void router_kernel(const float* __restrict__ x,
                              const float* __restrict__ Wr,
                              const float* __restrict__ br,
                              const float* __restrict__ gum) {
    int t = blockIdx.x;
    int tid = threadIdx.x;  // 128
    const float* xr = x + (size_t)t * Dn;
    float acc[En];
#pragma unroll
    for (int e = 0; e < En; e++) acc[e] = 0.f;
    for (int d = tid; d < Dn; d += 128) {
        float xv = xr[d];
        float4 w0 = *(const float4*)(Wr + d * En);
        float4 w1 = *(const float4*)(Wr + d * En + 4);
        acc[0] += xv * w0.x; acc[1] += xv * w0.y;
        acc[2] += xv * w0.z; acc[3] += xv * w0.w;
        acc[4] += xv * w1.x; acc[5] += xv * w1.y;
        acc[6] += xv * w1.z; acc[7] += xv * w1.w;
    }
#pragma unroll
    for (int e = 0; e < En; e++) {
#pragma unroll
        for (int off = 16; off; off >>= 1)
            acc[e] += __shfl_down_sync(0xffffffffu, acc[e], off);
    }
    __shared__ float red[4][En];
    if ((tid & 31) == 0) {
#pragma unroll
        for (int e = 0; e < En; e++) red[tid >> 5][e] = acc[e];
    }
    __syncthreads();
    if (tid == 0) {
        float s[En];
#pragma unroll
        for (int e = 0; e < En; e++)
            s[e] = red[0][e] + red[1][e] + red[2][e] + red[3][e]
                 + br[e] + gum[(size_t)t * En + e];
        int i1 = 0;
#pragma unroll
        for (int e = 1; e < En; e++) if (s[e] > s[i1]) i1 = e;
        int i2 = (i1 == 0) ? 1 : 0;
#pragma unroll
        for (int e = 0; e < En; e++)
            if (e != i1 && s[e] > s[i2]) i2 = e;
        int p1 = atomicAdd(&g_cnt[i1], 1); g_list[i1 * Tn + p1] = t;
        int p2 = atomicAdd(&g_cnt[i2], 1); g_list[i2 * Tn + p2] = t;
    }
}

// ---------------- conversions ----------------
__global__ void ext_x_kernel(const float* __restrict__ x) {
    int idx = blockIdx.x * 256 + threadIdx.x;
    if (idx >= Tn * Dn) return;
    int t = idx / Dn, d = idx - t * Dn;
    float v = x[idx];
    __half hi = __float2half_rn(v);
    g_Xe[(size_t)t * (2 * Dn) + d] = hi;
    g_Xe[(size_t)t * (2 * Dn) + Dn + d] = __float2half_rn(v - __half2float(hi));
}

// Transpose: src [z][SK][SN] fp32 -> g_We [zBase+z][SN][SK] fp16
template <int SK, int SN>
__global__ void ext_w_kernel(const float* __restrict__ W, int zBase) {
    __shared__ float tile[32][33];
    int n0 = blockIdx.x * 32, k0 = blockIdx.y * 32;
    const float* Wz = W + (size_t)blockIdx.z * SK * SN;
    __half* dst = g_We + (size_t)(zBase + blockIdx.z) * SN * (size_t)SK;
    int tx = threadIdx.x, ty = threadIdx.y;
#pragma unroll
    for (int r = 0; r < 32; r += 8)
        tile[ty + r][tx] = Wz[(size_t)(k0 + ty + r) * SN + n0 + tx];
    __syncthreads();
#pragma unroll
    for (int r = 0; r < 32; r += 8)
        dst[(size_t)(n0 + ty + r) * SK + (k0 + tx)] = __float2half_rn(tile[tx][ty + r]);
}

// ---------------- mma.sync fp16 GEMM: BM=BN=128, warp tile 32x64, 2 passes ----------------
#define BM 128
#define BN 128
#define BK 32
#define STAGES 3
#define ROWPB 80                      // padded row pitch in bytes (40 halves)
#define TILEB (128 * ROWPB)           // 10240 B per operand tile
#define STGB (2 * TILEB)              // 20480 B per stage
#define SMEMT (STAGES * STGB)         // 61440 B

// IS1: He[row] = split(gelu(X@W1+b1));  !IS1: out[tok] += H@W2+b2
template <int KD, int NT, bool GATHER, bool IS1>
__global__ void __launch_bounds__(256, 2)
moe_gemm(const float* __restrict__ bias, float* __restrict__ outF) {
    int z = blockIdx.z;
    int M = GATHER ? g_cnt[z] : Tn;
    int m0 = blockIdx.y * BM;
    if (m0 >= M) return;
    int n0 = blockIdx.x * BN;
    int tid = threadIdx.x, lane = tid & 31, wid = tid >> 5;
    int wm = wid & 3, wn = wid >> 2;     // 4 x 2 warp grid; warp tile 32m x 64n

    extern __shared__ __align__(1024) char smem[];
    uint32_t sb = smem_u32(smem);

    size_t rowBase = GATHER ? (size_t)g_off[z] : (size_t)(ROUTED_ROWS + (size_t)z * Tn);
    // A loader: row = tid>>1, 32B chunk = (tid&1); A rows are hi|lo (2*KD halves)
    int arow = m0 + (tid >> 1);
    int rr = (arow < M) ? arow : (M - 1);
    const __half* aRow;
    if (IS1) {
        int tok = GATHER ? g_list[z * Tn + rr] : rr;
        aRow = g_Xe + (size_t)tok * (2 * KD);
    } else {
        aRow = g_He + (rowBase + rr) * (size_t)(2 * KD);
    }
    int zw = GATHER ? z : (En + z);
    const __half* bRowW = g_We + ((size_t)zw * NT + n0 + (tid >> 1)) * (size_t)KD;

    const int IT = KD / BK;
    const int nIter = 2 * IT;   // segments: Ah*B, Al*B
    uint32_t stBase = sb + (tid >> 1) * ROWPB + (tid & 1) * 32;
    int ldCol = (tid & 1) * 16;

    float d[2][8][4];
#pragma unroll
    for (int a = 0; a < 2; a++)
#pragma unroll
        for (int b = 0; b < 8; b++)
#pragma unroll
            for (int c = 0; c < 4; c++) d[a][b][c] = 0.f;

    auto loadStage = [&](int j, int s) {
        int seg = j / IT, kk = j - seg * IT;
        int aOff = seg * KD + kk * BK + ldCol;
        int bOff = kk * BK + ldCol;
        uint32_t sa = stBase + s * STGB;
        cp16(sa,      aRow + aOff);
        cp16(sa + 16, aRow + aOff + 8);
        uint32_t sB = sa + TILEB;
        cp16(sB,      bRowW + bOff);
        cp16(sB + 16, bRowW + bOff + 8);
    };

    loadStage(0, 0);
    asm volatile("cp.async.commit_group;" ::: "memory");
    loadStage(1, 1);
    asm volatile("cp.async.commit_group;" ::: "memory");

    int lrow = lane & 15, lcol = (lane >> 4) * 16;
    for (int j = 0; j < nIter; j++) {
        int s = j % STAGES;
        asm volatile("cp.async.wait_group 1;" ::: "memory");
        __syncthreads();
        int jn = j + 2;
        if (jn < nIter) loadStage(jn, jn % STAGES);
        asm volatile("cp.async.commit_group;" ::: "memory");

        uint32_t Ab = sb + s * STGB;
        uint32_t Bb = Ab + TILEB;
#pragma unroll
        for (int k16 = 0; k16 < 2; k16++) {
            uint32_t af[2][4];
#pragma unroll
            for (int mi = 0; mi < 2; mi++)
                ldsm4(af[mi], Ab + (wm * 32 + mi * 16 + lrow) * ROWPB + k16 * 32 + lcol);
            uint32_t bf[4][4];
#pragma unroll
            for (int g = 0; g < 4; g++)
                ldsm4(bf[g], Bb + (wn * 64 + g * 16 + lrow) * ROWPB + k16 * 32 + lcol);
#pragma unroll
            for (int mi = 0; mi < 2; mi++)
#pragma unroll
                for (int t = 0; t < 8; t++) {
                    int g = t >> 1, w = t & 1;
                    mma16816(d[mi][t], af[mi], bf[g][w], bf[g][2 + w]);
                }
        }
    }

    // ---- epilogue ----
    const float* bz = bias + (size_t)z * NT;
    int cb = n0 + wn * 64 + (lane & 3) * 2;
    int r0 = m0 + wm * 32 + (lane >> 2);
#pragma unroll
    for (int mi = 0; mi < 2; mi++) {
#pragma unroll
        for (int half = 0; half < 2; half++) {   // regs {0,1} row r, {2,3} row r+8
            int row = r0 + mi * 16 + half * 8;
            if (row >= M) continue;
            if (IS1) {
                __half* dstH = g_He + (rowBase + row) * (size_t)(2 * NT);
#pragma unroll
                for (int ni = 0; ni < 8; ni++) {
                    int col = cb + ni * 8;
                    float v0 = gelu_f(d[mi][ni][half * 2 + 0] + bz[col]);
                    float v1 = gelu_f(d[mi][ni][half * 2 + 1] + bz[col + 1]);
                    __half h0 = __float2half_rn(v0);
                    __half h1 = __float2half_rn(v1);
                    __half l0 = __float2half_rn(v0 - __half2float(h0));
                    __half l1 = __float2half_rn(v1 - __half2float(h1));
                    uint32_t ph = ((uint32_t)*(uint16_t*)&h1 << 16) | *(uint16_t*)&h0;
                    uint32_t pl = ((uint32_t)*(uint16_t*)&l1 << 16) | *(uint16_t*)&l0;
                    *(uint32_t*)(dstH + col) = ph;
                    *(uint32_t*)(dstH + NT + col) = pl;
                }
            } else {
                int g = GATHER ? g_list[z * Tn + row] : row;
                float* od = outF + (size_t)g * Dn;
#pragma unroll
                for (int ni = 0; ni < 8; ni++) {
                    int col = cb + ni * 8;
                    atomicAdd(&od[col],     d[mi][ni][half * 2 + 0] + bz[col]);
                    atomicAdd(&od[col + 1], d[mi][ni][half * 2 + 1] + bz[col + 1]);
                }
            }
        }
    }
}

extern "C" void kernel_launch(void* const* d_in, const int* in_sizes, int n_in,
                              void* d_out, int out_size) {
    const float* x   = (const float*)d_in[0];
    const float* Ws1 = (const float*)d_in[1];
    const float* bs1 = (const float*)d_in[2];
    const float* Ws2 = (const float*)d_in[3];
    const float* bs2 = (const float*)d_in[4];
    const float* We1 = (const float*)d_in[5];
    const float* be1 = (const float*)d_in[6];
    const float* We2 = (const float*)d_in[7];
    const float* be2 = (const float*)d_in[8];
    const float* Wr  = (const float*)d_in[9];
    const float* br  = (const float*)d_in[10];
    const float* gum = (const float*)d_in[11];
    float* out = (float*)d_out;

    cudaFuncSetAttribute(moe_gemm<Dn, Hn, true,  true >, cudaFuncAttributeMaxDynamicSharedMemorySize, SMEMT);
    cudaFuncSetAttribute(moe_gemm<Dn, Hn, false, true >, cudaFuncAttributeMaxDynamicSharedMemorySize, SMEMT);
    cudaFuncSetAttribute(moe_gemm<Hn, Dn, true,  false>, cudaFuncAttributeMaxDynamicSharedMemorySize, SMEMT);
    cudaFuncSetAttribute(moe_gemm<Hn, Dn, false, false>, cudaFuncAttributeMaxDynamicSharedMemorySize, SMEMT);

    cudaMemsetAsync(out, 0, (size_t)out_size * sizeof(float), 0);
    zero_cnt_kernel<<<1, 32>>>();
    router_kernel<<<Tn, 128>>>(x, Wr, br, gum);
    prefix_kernel<<<1, 32>>>();

    ext_x_kernel<<<(Tn * Dn) / 256, 256>>>(x);
    dim3 bw(32, 8);

    // Phase 1: W1^T into g_We, then FFN1 (routed + shared).
    ext_w_kernel<Dn, Hn><<<dim3(Hn / 32, Dn / 32, En ), bw>>>(We1, 0);
    ext_w_kernel<Dn, Hn><<<dim3(Hn / 32, Dn / 32, NSn), bw>>>(Ws1, En);
    moe_gemm<Dn, Hn, true,  true ><<<dim3(Hn / BN, Tn / BM, En ), 256, SMEMT>>>(be1, nullptr);
    moe_gemm<Dn, Hn, false, true ><<<dim3(Hn / BN, Tn / BM, NSn), 256, SMEMT>>>(bs1, nullptr);

    // Phase 2: W2^T overwrites g_We (stream-ordered after FFN1), then FFN2.
    ext_w_kernel<Hn, Dn><<<dim3(Dn / 32, Hn / 32, En ), bw>>>(We2, 0);
    ext_w_kernel<Hn, Dn><<<dim3(Dn / 32, Hn / 32, NSn), bw>>>(Ws2, En);
    moe_gemm<Hn, Dn, true,  false><<<dim3(Dn / BN, Tn / BM, En ), 256, SMEMT>>>(be2, out);
    moe_gemm<Hn, Dn, false, false><<<dim3(Dn / BN, Tn / BM, NSn), 256, SMEMT>>>(bs2, out);
}

// round 10
// speedup vs baseline: 2.8223x; 1.7532x over previous
#include <cuda_runtime.h>
#include <cuda_fp16.h>
#include <cstdint>
#include <math.h>

#define Tn 4096
#define Dn 1024
#define Hn 4096
#define En 8
#define NSn 2
#define NEn (En + NSn)
#define ROUTED_ROWS (2 * Tn)
#define ALLROWS (ROUTED_ROWS + NSn * Tn)

// ---- static scratch (no allocation APIs); aligned for cp.async 16B ----
__device__ __align__(1024) __half g_Xe[(size_t)Tn * Dn];          // x fp16 [t][D] (8MB)
// Shared weight buffer: W1^T fp16 [z][H][D] during FFN1, then W2^T fp16 [z][D][H]. (80MB)
__device__ __align__(1024) __half g_We[(size_t)NEn * Hn * Dn];
__device__ __align__(1024) __half g_He[(size_t)ALLROWS * Hn];     // hidden fp16 (128MB)
__device__ int g_cnt[En];
__device__ int g_off[En];
__device__ int g_list[En * Tn];

// ---------------- PTX helpers (non-'a' features only) ----------------
__device__ __forceinline__ uint32_t smem_u32(const void* p) {
    uint32_t a;
    asm("{ .reg .u64 t; cvta.to.shared.u64 t, %1; cvt.u32.u64 %0, t; }" : "=r"(a) : "l"(p));
    return a;
}
__device__ __forceinline__ void cp16(uint32_t s, const void* g) {
    asm volatile("cp.async.cg.shared.global [%0], [%1], 16;" :: "r"(s), "l"(g));
}
__device__ __forceinline__ void ldsm4(uint32_t* r, uint32_t a) {
    asm volatile("ldmatrix.sync.aligned.m8n8.x4.shared.b16 {%0,%1,%2,%3}, [%4];"
                 : "=r"(r[0]), "=r"(r[1]), "=r"(r[2]), "=r"(r[3]) : "r"(a));
}
__device__ __forceinline__ void mma16816(float* d, const uint32_t* a, uint32_t b0, uint32_t b1) {
    asm volatile(
        "mma.sync.aligned.m16n8k16.row.col.f32.f16.f16.f32 "
        "{%0,%1,%2,%3}, {%4,%5,%6,%7}, {%8,%9}, {%0,%1,%2,%3};"
        : "+f"(d[0]), "+f"(d[1]), "+f"(d[2]), "+f"(d[3])
        : "r"(a[0]), "r"(a[1]), "r"(a[2]), "r"(a[3]), "r"(b0), "r"(b1));
}
__device__ __forceinline__ float gelu_f(float v) {
    float u = 0.7978845608028654f * (v + 0.044715f * v * v * v);
    float t;
    asm("tanh.approx.f32 %0, %1;" : "=f"(t) : "f"(u));
    return 0.5f * v * (1.0f + t);
}

// ---------------- router ----------------
__global__ void zero_cnt_kernel() {
    if (threadIdx.x < En) g_cnt[threadIdx.x] = 0;
}
__global__ void prefix_kernel() {
    if (threadIdx.x == 0) {
        int s = 0;
#pragma unroll
        for (int e = 0; e < En; e++) { g_off[e] = s; s += g_cnt[e]; }
    }
}
__global__ void router_kernel(const float* __restrict__ x,
                              const float* __restrict__ Wr,
                              const float* __restrict__ br,
                              const float* __restrict__ gum) {
    int t = blockIdx.x;
    int tid = threadIdx.x;  // 128
    const float* xr = x + (size_t)t * Dn;
    float acc[En];
#pragma unroll
    for (int e = 0; e < En; e++) acc[e] = 0.f;
    for (int d = tid; d < Dn; d += 128) {
        float xv = xr[d];
        float4 w0 = *(const float4*)(Wr + d * En);
        float4 w1 = *(const float4*)(Wr + d * En + 4);
        acc[0] += xv * w0.x; acc[1] += xv * w0.y;
        acc[2] += xv * w0.z; acc[3] += xv * w0.w;
        acc[4] += xv * w1.x; acc[5] += xv * w1.y;
        acc[6] += xv * w1.z; acc[7] += xv * w1.w;
    }
#pragma unroll
    for (int e = 0; e < En; e++) {
#pragma unroll
        for (int off = 16; off; off >>= 1)
            acc[e] += __shfl_down_sync(0xffffffffu, acc[e], off);
    }
    __shared__ float red[4][En];
    if ((tid & 31) == 0) {
#pragma unroll
        for (int e = 0; e < En; e++) red[tid >> 5][e] = acc[e];
    }
    __syncthreads();
    if (tid == 0) {
        float s[En];
#pragma unroll
        for (int e = 0; e < En; e++)
            s[e] = red[0][e] + red[1][e] + red[2][e] + red[3][e]
                 + br[e] + gum[(size_t)t * En + e];
        int i1 = 0;
#pragma unroll
        for (int e = 1; e < En; e++) if (s[e] > s[i1]) i1 = e;
        int i2 = (i1 == 0) ? 1 : 0;
#pragma unroll
        for (int e = 0; e < En; e++)
            if (e != i1 && s[e] > s[i2]) i2 = e;
        int p1 = atomicAdd(&g_cnt[i1], 1); g_list[i1 * Tn + p1] = t;
        int p2 = atomicAdd(&g_cnt[i2], 1); g_list[i2 * Tn + p2] = t;
    }
}

// ---------------- conversions ----------------
__global__ void ext_x_kernel(const float* __restrict__ x) {
    int idx = blockIdx.x * 256 + threadIdx.x;   // one float4 per thread
    if (idx * 4 >= Tn * Dn) return;
    float4 v = *(const float4*)(x + idx * 4);
    __half2 a = __floats2half2_rn(v.x, v.y);
    __half2 b = __floats2half2_rn(v.z, v.w);
    *(uint2*)(g_Xe + idx * 4) = make_uint2(*(uint32_t*)&a, *(uint32_t*)&b);
}

// Transpose: src [z][SK][SN] fp32 -> g_We [zBase+z][SN][SK] fp16
template <int SK, int SN>
__global__ void ext_w_kernel(const float* __restrict__ W, int zBase) {
    __shared__ float tile[32][33];
    int n0 = blockIdx.x * 32, k0 = blockIdx.y * 32;
    const float* Wz = W + (size_t)blockIdx.z * SK * SN;
    __half* dst = g_We + (size_t)(zBase + blockIdx.z) * SN * (size_t)SK;
    int tx = threadIdx.x, ty = threadIdx.y;
#pragma unroll
    for (int r = 0; r < 32; r += 8)
        tile[ty + r][tx] = Wz[(size_t)(k0 + ty + r) * SN + n0 + tx];
    __syncthreads();
#pragma unroll
    for (int r = 0; r < 32; r += 8)
        dst[(size_t)(n0 + ty + r) * SK + (k0 + tx)] = __float2half_rn(tile[tx][ty + r]);
}

// ---------------- mma.sync fp16 GEMM: BM=BN=128, warp tile 32x64, single pass ----------------
#define BM 128
#define BN 128
#define BK 32
#define STAGES 3
#define ROWPB 80                      // padded row pitch in bytes (40 halves)
#define TILEB (128 * ROWPB)           // 10240 B per operand tile
#define STGB (2 * TILEB)              // 20480 B per stage
#define SMEMT (STAGES * STGB)         // 61440 B

// IS1: He[row] = fp16(gelu(X@W1+b1));  !IS1: out[tok] += H@W2+b2
template <int KD, int NT, bool GATHER, bool IS1>
__global__ void __launch_bounds__(256, 2)
moe_gemm(const float* __restrict__ bias, float* __restrict__ outF) {
    int z = blockIdx.z;
    int M = GATHER ? g_cnt[z] : Tn;
    int m0 = blockIdx.y * BM;
    if (m0 >= M) return;
    int n0 = blockIdx.x * BN;
    int tid = threadIdx.x, lane = tid & 31, wid = tid >> 5;
    int wm = wid & 3, wn = wid >> 2;     // 4 x 2 warp grid; warp tile 32m x 64n

    extern __shared__ __align__(1024) char smem[];
    uint32_t sb = smem_u32(smem);

    size_t rowBase = GATHER ? (size_t)g_off[z] : (size_t)(ROUTED_ROWS + (size_t)z * Tn);
    // A loader: row = tid>>1, 32B chunk = (tid&1)
    int arow = m0 + (tid >> 1);
    int rr = (arow < M) ? arow : (M - 1);
    const __half* aRow;
    if (IS1) {
        int tok = GATHER ? g_list[z * Tn + rr] : rr;
        aRow = g_Xe + (size_t)tok * KD;
    } else {
        aRow = g_He + (rowBase + rr) * (size_t)KD;
    }
    int zw = GATHER ? z : (En + z);
    const __half* bRowW = g_We + ((size_t)zw * NT + n0 + (tid >> 1)) * (size_t)KD;

    const int nIter = KD / BK;
    uint32_t stBase = sb + (tid >> 1) * ROWPB + (tid & 1) * 32;
    int ldCol = (tid & 1) * 16;

    float d[2][8][4];
#pragma unroll
    for (int a = 0; a < 2; a++)
#pragma unroll
        for (int b = 0; b < 8; b++)
#pragma unroll
            for (int c = 0; c < 4; c++) d[a][b][c] = 0.f;

    auto loadStage = [&](int j, int s) {
        int off0 = j * BK + ldCol;
        uint32_t sa = stBase + s * STGB;
        cp16(sa,      aRow + off0);
        cp16(sa + 16, aRow + off0 + 8);
        uint32_t sB = sa + TILEB;
        cp16(sB,      bRowW + off0);
        cp16(sB + 16, bRowW + off0 + 8);
    };

    loadStage(0, 0);
    asm volatile("cp.async.commit_group;" ::: "memory");
    loadStage(1, 1);
    asm volatile("cp.async.commit_group;" ::: "memory");

    int lrow = lane & 15, lcol = (lane >> 4) * 16;
    for (int j = 0; j < nIter; j++) {
        int s = j % STAGES;
        asm volatile("cp.async.wait_group 1;" ::: "memory");
        __syncthreads();
        int jn = j + 2;
        if (jn < nIter) loadStage(jn, jn % STAGES);
        asm volatile("cp.async.commit_group;" ::: "memory");

        uint32_t Ab = sb + s * STGB;
        uint32_t Bb = Ab + TILEB;
#pragma unroll
        for (int k16 = 0; k16 < 2; k16++) {
            uint32_t af[2][4];
#pragma unroll
            for (int mi = 0; mi < 2; mi++)
                ldsm4(af[mi], Ab + (wm * 32 + mi * 16 + lrow) * ROWPB + k16 * 32 + lcol);
            uint32_t bf[4][4];
#pragma unroll
            for (int g = 0; g < 4; g++)
                ldsm4(bf[g], Bb + (wn * 64 + g * 16 + lrow) * ROWPB + k16 * 32 + lcol);
#pragma unroll
            for (int mi = 0; mi < 2; mi++)
#pragma unroll
                for (int t = 0; t < 8; t++) {
                    int g = t >> 1, w = t & 1;
                    mma16816(d[mi][t], af[mi], bf[g][w], bf[g][2 + w]);
                }
        }
    }

    // ---- epilogue ----
    const float* bz = bias + (size_t)z * NT;
    int cb = n0 + wn * 64 + (lane & 3) * 2;
    int r0 = m0 + wm * 32 + (lane >> 2);
#pragma unroll
    for (int mi = 0; mi < 2; mi++) {
#pragma unroll
        for (int half = 0; half < 2; half++) {   // regs {0,1} row r, {2,3} row r+8
            int row = r0 + mi * 16 + half * 8;
            if (row >= M) continue;
            if (IS1) {
                __half* dstH = g_He + (rowBase + row) * (size_t)NT;
#pragma unroll
                for (int ni = 0; ni < 8; ni++) {
                    int col = cb + ni * 8;
                    float v0 = gelu_f(d[mi][ni][half * 2 + 0] + bz[col]);
                    float v1 = gelu_f(d[mi][ni][half * 2 + 1] + bz[col + 1]);
                    __half2 p = __floats2half2_rn(v0, v1);
                    *(uint32_t*)(dstH + col) = *(uint32_t*)&p;
                }
            } else {
                int g = GATHER ? g_list[z * Tn + row] : row;
                float* od = outF + (size_t)g * Dn;
#pragma unroll
                for (int ni = 0; ni < 8; ni++) {
                    int col = cb + ni * 8;
                    atomicAdd(&od[col],     d[mi][ni][half * 2 + 0] + bz[col]);
                    atomicAdd(&od[col + 1], d[mi][ni][half * 2 + 1] + bz[col + 1]);
                }
            }
        }
    }
}

extern "C" void kernel_launch(void* const* d_in, const int* in_sizes, int n_in,
                              void* d_out, int out_size) {
    const float* x   = (const float*)d_in[0];
    const float* Ws1 = (const float*)d_in[1];
    const float* bs1 = (const float*)d_in[2];
    const float* Ws2 = (const float*)d_in[3];
    const float* bs2 = (const float*)d_in[4];
    const float* We1 = (const float*)d_in[5];
    const float* be1 = (const float*)d_in[6];
    const float* We2 = (const float*)d_in[7];
    const float* be2 = (const float*)d_in[8];
    const float* Wr  = (const float*)d_in[9];
    const float* br  = (const float*)d_in[10];
    const float* gum = (const float*)d_in[11];
    float* out = (float*)d_out;

    cudaFuncSetAttribute(moe_gemm<Dn, Hn, true,  true >, cudaFuncAttributeMaxDynamicSharedMemorySize, SMEMT);
    cudaFuncSetAttribute(moe_gemm<Dn, Hn, false, true >, cudaFuncAttributeMaxDynamicSharedMemorySize, SMEMT);
    cudaFuncSetAttribute(moe_gemm<Hn, Dn, true,  false>, cudaFuncAttributeMaxDynamicSharedMemorySize, SMEMT);
    cudaFuncSetAttribute(moe_gemm<Hn, Dn, false, false>, cudaFuncAttributeMaxDynamicSharedMemorySize, SMEMT);

    cudaMemsetAsync(out, 0, (size_t)out_size * sizeof(float), 0);
    zero_cnt_kernel<<<1, 32>>>();
    router_kernel<<<Tn, 128>>>(x, Wr, br, gum);
    prefix_kernel<<<1, 32>>>();

    ext_x_kernel<<<(Tn * Dn) / 1024, 256>>>(x);
    dim3 bw(32, 8);

    // Phase 1: W1^T into g_We, then FFN1 (routed + shared).
    ext_w_kernel<Dn, Hn><<<dim3(Hn / 32, Dn / 32, En ), bw>>>(We1, 0);
    ext_w_kernel<Dn, Hn><<<dim3(Hn / 32, Dn / 32, NSn), bw>>>(Ws1, En);
    moe_gemm<Dn, Hn, true,  true ><<<dim3(Hn / BN, Tn / BM, En ), 256, SMEMT>>>(be1, nullptr);
    moe_gemm<Dn, Hn, false, true ><<<dim3(Hn / BN, Tn / BM, NSn), 256, SMEMT>>>(bs1, nullptr);

    // Phase 2: W2^T overwrites g_We (stream-ordered after FFN1), then FFN2.
    ext_w_kernel<Hn, Dn><<<dim3(Dn / 32, Hn / 32, En ), bw>>>(We2, 0);
    ext_w_kernel<Hn, Dn><<<dim3(Dn / 32, Hn / 32, NSn), bw>>>(Ws2, En);
    moe_gemm<Hn, Dn, true,  false><<<dim3(Dn / BN, Tn / BM, En ), 256, SMEMT>>>(be2, out);
    moe_gemm<Hn, Dn, false, false><<<dim3(Dn / BN, Tn / BM, NSn), 256, SMEMT>>>(bs2, out);
}